// round 5
// baseline (speedup 1.0000x reference)
#include <cuda_runtime.h>

// RoiPoolingConv: bilinear 7x7 ROI pooling over NHWC feat (1,200,200,512) fp32.
// out shape (1, 300, 7, 7, 512) fp32.
//
// d_in[0]: feat  float32  [1,200,200,512]
// d_in[1]: rois  int32    [1,300,4]  (x0, y0, w, h)
//
// R5: persistent CTAs (148*8) with software-pipelined grid-stride cell loop:
//     issue next cell's 4 corner loads before blending the current cell,
//     keeping a continuous load stream into L2 (attack LTS duty cycle).

#define POOL 7
#define NUM_ROIS 300
#define FH 200
#define FW 200
#define FC 512
#define TOTAL_CELLS (NUM_ROIS * POOL * POOL)   // 14700
#define NBLOCKS (148 * 8)                      // persistent grid

struct Geom {
    const float4* p00;
    const float4* p01;
    const float4* p10;
    const float4* p11;
    float fx, fy;
    int idx;
};

__device__ __forceinline__ Geom make_geom(const float* __restrict__ feat,
                                          const int* __restrict__ rois,
                                          int idx) {
    const int roi  = idx / (POOL * POOL);
    const int cell = idx - roi * (POOL * POOL);
    const int py = cell / POOL;
    const int px = cell - py * POOL;

    const int4 r = __ldg(((const int4*)rois) + roi);
    const int x0 = r.x, y0 = r.y, w = r.z, h = r.w;

    // Match reference math exactly:
    //   sy = py * (h/7), y_lo = floor(sy), y_hi = min(y_lo+1, h-1), fy = sy - y_lo
    const float sy = (float)py * ((float)h / (float)POOL);
    const float sx = (float)px * ((float)w / (float)POOL);
    const int y_lo = (int)floorf(sy);
    const int x_lo = (int)floorf(sx);
    const int y_hi = min(y_lo + 1, h - 1);
    const int x_hi = min(x_lo + 1, w - 1);

    Geom g;
    g.idx = idx;
    g.fy = sy - (float)y_lo;
    g.fx = sx - (float)x_lo;

    const int ay_lo = y0 + y_lo, ay_hi = y0 + y_hi;
    const int ax_lo = x0 + x_lo, ax_hi = x0 + x_hi;

    g.p00 = (const float4*)(feat + ((size_t)ay_lo * FW + ax_lo) * FC);
    g.p01 = (const float4*)(feat + ((size_t)ay_lo * FW + ax_hi) * FC);
    g.p10 = (const float4*)(feat + ((size_t)ay_hi * FW + ax_lo) * FC);
    g.p11 = (const float4*)(feat + ((size_t)ay_hi * FW + ax_hi) * FC);
    return g;
}

__device__ __forceinline__ void blend_store(const Geom& g, int c4,
                                            float4 v00, float4 v01,
                                            float4 v10, float4 v11,
                                            float* __restrict__ out) {
    const float gx = 1.0f - g.fx;
    const float gy = 1.0f - g.fy;
    float4 o;
    float top, bot;
    top = v00.x * gx + v01.x * g.fx;
    bot = v10.x * gx + v11.x * g.fx;
    o.x = top * gy + bot * g.fy;
    top = v00.y * gx + v01.y * g.fx;
    bot = v10.y * gx + v11.y * g.fx;
    o.y = top * gy + bot * g.fy;
    top = v00.z * gx + v01.z * g.fx;
    bot = v10.z * gx + v11.z * g.fx;
    o.z = top * gy + bot * g.fy;
    top = v00.w * gx + v01.w * g.fx;
    bot = v10.w * gx + v11.w * g.fx;
    o.w = top * gy + bot * g.fy;

    float4* outp = (float4*)(out + (size_t)g.idx * FC);
    __stcs(outp + c4, o);
}

__global__ __launch_bounds__(128, 8)
void roi_pool_kernel(const float* __restrict__ feat,
                     const int* __restrict__ rois,
                     float* __restrict__ out) {
    const int c4 = threadIdx.x;          // channel quad 0..127
    int idx = blockIdx.x;                // flat (roi,cell), cell fastest

    if (idx >= TOTAL_CELLS) return;      // (never with NBLOCKS<TOTAL, kept safe)

    // Prologue: stage cell 0
    Geom g = make_geom(feat, rois, idx);
    float4 v00 = __ldg(g.p00 + c4);
    float4 v01 = __ldg(g.p01 + c4);
    float4 v10 = __ldg(g.p10 + c4);
    float4 v11 = __ldg(g.p11 + c4);

    int next = idx + NBLOCKS;
    while (next < TOTAL_CELLS) {
        // Issue next cell's loads first (in flight during current blend).
        Geom g2 = make_geom(feat, rois, next);
        float4 w00 = __ldg(g2.p00 + c4);
        float4 w01 = __ldg(g2.p01 + c4);
        float4 w10 = __ldg(g2.p10 + c4);
        float4 w11 = __ldg(g2.p11 + c4);

        // Blend + store current (loads from last iteration are ready by now).
        blend_store(g, c4, v00, v01, v10, v11, out);

        g = g2;
        v00 = w00; v01 = w01; v10 = w10; v11 = w11;
        next += NBLOCKS;
    }

    // Epilogue: final staged cell.
    blend_store(g, c4, v00, v01, v10, v11, out);
}

extern "C" void kernel_launch(void* const* d_in, const int* in_sizes, int n_in,
                              void* d_out, int out_size) {
    const float* feat = (const float*)d_in[0];
    const int*   rois = (const int*)d_in[1];
    float*       out  = (float*)d_out;

    roi_pool_kernel<<<NBLOCKS, 128>>>(feat, rois, out);
}

// round 6
// speedup vs baseline: 1.1359x; 1.1359x over previous
#include <cuda_runtime.h>

// RoiPoolingConv: bilinear 7x7 ROI pooling over NHWC feat (1,200,200,512) fp32.
// out shape (1, 300, 7, 7, 512) fp32.
//
// d_in[0]: feat  float32  [1,200,200,512]
// d_in[1]: rois  int32    [1,300,4]  (x0, y0, w, h)
//
// R6: R4 per-thread code (4x LDG.128 + blend + STG.128, ~30 regs) but 2 cells
//     per 256-thread CTA (warps 0-3 -> cell pair, warps 4-7 -> cell pair+25).
//     Register-neutral concurrency: fewer CTAs/waves, amortized ROI load,
//     shared-row L1 co-residency between the two cells.

#define POOL 7
#define NUM_ROIS 300
#define FH 200
#define FW 200
#define FC 512

__global__ __launch_bounds__(256, 8)
void roi_pool_kernel(const float* __restrict__ feat,
                     const int* __restrict__ rois,
                     float* __restrict__ out) {
    const int pair = blockIdx.x;          // 0..24
    const int roi  = blockIdx.y;          // 0..299
    const int half = threadIdx.x >> 7;    // 0: cellA, 1: cellB
    const int c4   = threadIdx.x & 127;   // channel quad 0..127

    int cell = pair + half * 25;          // A: 0..24, B: 25..49
    const bool valid = (cell < POOL * POOL);
    if (!valid) cell = pair;              // dup geometry; store suppressed

    const int4 r = __ldg(((const int4*)rois) + roi);
    const int x0 = r.x, y0 = r.y, w = r.z, h = r.w;

    const int py = cell / POOL;
    const int px = cell - py * POOL;

    // Match reference math exactly:
    //   sy = py * (h/7), y_lo = floor(sy), y_hi = min(y_lo+1, h-1), fy = sy - y_lo
    const float sy = (float)py * ((float)h / (float)POOL);
    const float sx = (float)px * ((float)w / (float)POOL);
    const int y_lo = (int)floorf(sy);
    const int x_lo = (int)floorf(sx);
    const int y_hi = min(y_lo + 1, h - 1);
    const int x_hi = min(x_lo + 1, w - 1);
    const float fy = sy - (float)y_lo;
    const float fx = sx - (float)x_lo;

    const int ay_lo = y0 + y_lo, ay_hi = y0 + y_hi;
    const int ax_lo = x0 + x_lo, ax_hi = x0 + x_hi;

    // Channel-contiguous NHWC: feat[(y*FW + x)*FC + c]
    const float4* p00 = (const float4*)(feat + ((size_t)ay_lo * FW + ax_lo) * FC);
    const float4* p01 = (const float4*)(feat + ((size_t)ay_lo * FW + ax_hi) * FC);
    const float4* p10 = (const float4*)(feat + ((size_t)ay_hi * FW + ax_lo) * FC);
    const float4* p11 = (const float4*)(feat + ((size_t)ay_hi * FW + ax_hi) * FC);

    // 4 independent 16B loads in flight per thread.
    const float4 v00 = __ldg(p00 + c4);
    const float4 v01 = __ldg(p01 + c4);
    const float4 v10 = __ldg(p10 + c4);
    const float4 v11 = __ldg(p11 + c4);

    const float gx = 1.0f - fx;
    const float gy = 1.0f - fy;

    float4 o;
    {
        float top, bot;
        top = v00.x * gx + v01.x * fx;
        bot = v10.x * gx + v11.x * fx;
        o.x = top * gy + bot * fy;
        top = v00.y * gx + v01.y * fx;
        bot = v10.y * gx + v11.y * fx;
        o.y = top * gy + bot * fy;
        top = v00.z * gx + v01.z * fx;
        bot = v10.z * gx + v11.z * fx;
        o.z = top * gy + bot * fy;
        top = v00.w * gx + v01.w * fx;
        bot = v10.w * gx + v11.w * fx;
        o.w = top * gy + bot * fy;
    }

    if (valid) {
        // Streaming store: evict-first in L2, keep feat resident.
        float4* outp = (float4*)(out + (((size_t)roi * (POOL * POOL)) + cell) * FC);
        __stcs(outp + c4, o);
    }
}

extern "C" void kernel_launch(void* const* d_in, const int* in_sizes, int n_in,
                              void* d_out, int out_size) {
    const float* feat = (const float*)d_in[0];
    const int*   rois = (const int*)d_in[1];
    float*       out  = (float*)d_out;

    dim3 grid(25, NUM_ROIS);   // 2 cells per CTA
    roi_pool_kernel<<<grid, 256>>>(feat, rois, out);
}